// round 3
// baseline (speedup 1.0000x reference)
#include <cuda_runtime.h>

#define BB 64
#define TT 256
#define CC 384
#define HH 6
#define DD 64
#define BT (BB*TT)

typedef unsigned long long u64;

// Scratch (device globals: allocation-free per harness rules)
__device__ float g_Q[BB*HH*TT*DD];   // [b][h][t][d]
__device__ float g_K[BB*HH*TT*DD];
__device__ float g_V[BB*HH*TT*DD];
__device__ float g_A[BB*TT*CC];      // attention out, [b][t][h*64+d]

// ---- packed f32x2 helpers ---------------------------------------------------
__device__ __forceinline__ void fma2(u64 &d, u64 a, u64 b) {
    asm("fma.rn.f32x2 %0, %1, %2, %0;" : "+l"(d) : "l"(a), "l"(b));
}
__device__ __forceinline__ u64 dup2(float v) {
    u64 r;
    asm("mov.b64 %0, {%1, %1};" : "=l"(r) : "f"(v));
    return r;
}
__device__ __forceinline__ float2 unpk(u64 v) {
    float2 r;
    asm("mov.b64 {%0, %1}, %2;" : "=f"(r.x), "=f"(r.y) : "l"(v));
    return r;
}

// ---------------------------------------------------------------------------
// Kernel 1: QKV projections.  O[b,h,t,d] = sum_c x[b,t,c] * W[h,c,d]
// 64x64 tile, K-slab 16, 256 threads, 4x4 microtile done as 8 FFMA2/k-step.
// A-operand stored DUPLICATED ({a,a}) in smem so both packed operands are
// straight LDS.128 loads: 3 LDS.128 + 8 FFMA2 per k-step per thread.
// ---------------------------------------------------------------------------
__global__ __launch_bounds__(256) void qkv_kernel(
    const float* __restrict__ x,
    const float* __restrict__ Wq,
    const float* __restrict__ Wk,
    const float* __restrict__ Wv)
{
    __shared__ float2 Xs2[16][66];   // [k][m] = {a,a}; 66 -> 16B-aligned rows
    __shared__ float  Ws[16][64];    // [k][n]

    const int m0   = blockIdx.x * 64;
    const int proj = blockIdx.y / HH;
    const int h    = blockIdx.y % HH;
    const float* W = (proj == 0 ? Wq : (proj == 1 ? Wk : Wv)) + h * CC * DD;
    float* O       = (proj == 0 ? g_Q : (proj == 1 ? g_K : g_V));

    const int tid = threadIdx.x;
    const int tx  = tid & 15;      // col group (4 cols = 2 pairs)
    const int ty  = tid >> 4;      // row group (4 rows)
    const int lr  = tid >> 2;      // X loader: row 0..63
    const int lc4 = tid & 3;       // X loader: which float4 of 16 ks
    const int wk  = tid >> 4;      // W loader: k row 0..15
    const int wd4 = tid & 15;      // W loader: float4 col

    u64 c[4][2] = {};              // acc pairs along n: (n0,n1),(n2,n3)

    for (int kb = 0; kb < CC; kb += 16) {
        float4 xv = *(const float4*)(x + (m0 + lr) * CC + kb + lc4 * 4);
        Xs2[lc4*4+0][lr] = make_float2(xv.x, xv.x);
        Xs2[lc4*4+1][lr] = make_float2(xv.y, xv.y);
        Xs2[lc4*4+2][lr] = make_float2(xv.z, xv.z);
        Xs2[lc4*4+3][lr] = make_float2(xv.w, xv.w);
        *(float4*)(&Ws[wk][wd4*4]) = *(const float4*)(W + (kb + wk) * DD + wd4 * 4);
        __syncthreads();

        #pragma unroll
        for (int k = 0; k < 16; ++k) {
            ulonglong2 b01 = *(const ulonglong2*)(&Ws[k][tx*4]);     // (n0,n1),(n2,n3)
            ulonglong2 a01 = *(const ulonglong2*)(&Xs2[k][ty*4]);    // {m0,m0},{m1,m1}
            ulonglong2 a23 = *(const ulonglong2*)(&Xs2[k][ty*4+2]);  // {m2,m2},{m3,m3}
            fma2(c[0][0], a01.x, b01.x); fma2(c[0][1], a01.x, b01.y);
            fma2(c[1][0], a01.y, b01.x); fma2(c[1][1], a01.y, b01.y);
            fma2(c[2][0], a23.x, b01.x); fma2(c[2][1], a23.x, b01.y);
            fma2(c[3][0], a23.y, b01.x); fma2(c[3][1], a23.y, b01.y);
        }
        __syncthreads();
    }

    #pragma unroll
    for (int i = 0; i < 4; ++i) {
        int r = m0 + ty*4 + i;
        int b = r >> 8;
        int t = r & 255;
        float2 lo = unpk(c[i][0]);
        float2 hi = unpk(c[i][1]);
        *(float4*)(O + (((b*HH + h)*TT + t) * DD) + tx*4) =
            make_float4(lo.x, lo.y, hi.x, hi.y);
    }
}

// ---------------------------------------------------------------------------
// Kernel 2: fused causal attention, one block per (b,h).
// K,V (256x64 fp32 each) in 128 KB dynamic smem. Thread t owns query row t.
// All math in packed f32x2 pairs along D: 64 FFMA2 + 32 LDS.128 per s-step.
// Softmax without max-subtraction (scores tiny); exact same math as before.
// ---------------------------------------------------------------------------
__global__ __launch_bounds__(256) void attn_kernel()
{
    extern __shared__ float sm[];
    float* Ks = sm;                 // [256][64]
    float* Vs = sm + TT*DD;

    const int bh  = blockIdx.x;     // b*H + h
    const int tid = threadIdx.x;

    const float4* kg4 = (const float4*)(g_K + (size_t)bh * TT * DD);
    const float4* vg4 = (const float4*)(g_V + (size_t)bh * TT * DD);
    float4* Ks4 = (float4*)Ks;
    float4* Vs4 = (float4*)Vs;
    #pragma unroll
    for (int i = 0; i < (TT*DD/4)/256; ++i) {
        Ks4[tid + i*256] = kg4[tid + i*256];
        Vs4[tid + i*256] = vg4[tid + i*256];
    }
    __syncthreads();

    const int t = tid;
    u64 q2[32];                     // q pairs along d
    {
        const ulonglong2* qg = (const ulonglong2*)(g_Q + ((size_t)bh * TT + t) * DD);
        #pragma unroll
        for (int i = 0; i < 16; ++i) {
            ulonglong2 v = qg[i];
            q2[2*i] = v.x; q2[2*i+1] = v.y;
        }
    }

    u64 acc2[32];
    #pragma unroll
    for (int i = 0; i < 32; ++i) acc2[i] = 0ull;
    float l = 0.0f;
    const float scale = 0.125f;    // 1/sqrt(64)

    for (int s = 0; s <= t; ++s) {
        const ulonglong2* krow = (const ulonglong2*)(Ks + s * DD);
        u64 p0 = 0ull, p1 = 0ull, p2 = 0ull, p3 = 0ull;
        #pragma unroll
        for (int j = 0; j < 16; j += 2) {
            ulonglong2 ka = krow[j];
            ulonglong2 kb = krow[j+1];
            fma2(p0, q2[2*j+0], ka.x);
            fma2(p1, q2[2*j+1], ka.y);
            fma2(p2, q2[2*j+2], kb.x);
            fma2(p3, q2[2*j+3], kb.y);
        }
        float2 f0 = unpk(p0), f1 = unpk(p1), f2 = unpk(p2), f3 = unpk(p3);
        float sc = ((f0.x + f0.y) + (f1.x + f1.y)) + ((f2.x + f2.y) + (f3.x + f3.y));
        float e = __expf(sc * scale);
        l += e;
        u64 e2 = dup2(e);
        const ulonglong2* vrow = (const ulonglong2*)(Vs + s * DD);
        #pragma unroll
        for (int j = 0; j < 16; ++j) {
            ulonglong2 vv = vrow[j];
            fma2(acc2[2*j+0], e2, vv.x);
            fma2(acc2[2*j+1], e2, vv.y);
        }
    }

    const float inv = 1.0f / l;
    const int b = bh / HH, h = bh % HH;
    float4* og = (float4*)(g_A + ((size_t)(b*TT + t)) * CC + h * DD);
    #pragma unroll
    for (int i = 0; i < 16; ++i) {
        float2 lo = unpk(acc2[2*i]);
        float2 hi = unpk(acc2[2*i+1]);
        og[i] = make_float4(lo.x*inv, lo.y*inv, hi.x*inv, hi.y*inv);
    }
}

// ---------------------------------------------------------------------------
// Kernel 3: output projection.  out[r,n] = sum_c A[r,c]*Wp[c,n] + bp[n]
// Same f32x2 scheme as qkv. grid = (BT/64, 384/64)
// ---------------------------------------------------------------------------
__global__ __launch_bounds__(256) void proj_kernel(
    const float* __restrict__ Wp,
    const float* __restrict__ bp,
    float* __restrict__ out)
{
    __shared__ float2 Xs2[16][66];
    __shared__ float  Ws[16][64];

    const int m0 = blockIdx.x * 64;
    const int n0 = blockIdx.y * 64;

    const int tid = threadIdx.x;
    const int tx  = tid & 15;
    const int ty  = tid >> 4;
    const int lr  = tid >> 2;
    const int lc4 = tid & 3;
    const int wk  = tid >> 4;
    const int wd4 = tid & 15;

    u64 c[4][2] = {};

    for (int kb = 0; kb < CC; kb += 16) {
        float4 xv = *(const float4*)(g_A + (size_t)(m0 + lr) * CC + kb + lc4 * 4);
        Xs2[lc4*4+0][lr] = make_float2(xv.x, xv.x);
        Xs2[lc4*4+1][lr] = make_float2(xv.y, xv.y);
        Xs2[lc4*4+2][lr] = make_float2(xv.z, xv.z);
        Xs2[lc4*4+3][lr] = make_float2(xv.w, xv.w);
        *(float4*)(&Ws[wk][wd4*4]) = *(const float4*)(Wp + (size_t)(kb + wk) * CC + n0 + wd4 * 4);
        __syncthreads();

        #pragma unroll
        for (int k = 0; k < 16; ++k) {
            ulonglong2 b01 = *(const ulonglong2*)(&Ws[k][tx*4]);
            ulonglong2 a01 = *(const ulonglong2*)(&Xs2[k][ty*4]);
            ulonglong2 a23 = *(const ulonglong2*)(&Xs2[k][ty*4+2]);
            fma2(c[0][0], a01.x, b01.x); fma2(c[0][1], a01.x, b01.y);
            fma2(c[1][0], a01.y, b01.x); fma2(c[1][1], a01.y, b01.y);
            fma2(c[2][0], a23.x, b01.x); fma2(c[2][1], a23.x, b01.y);
            fma2(c[3][0], a23.y, b01.x); fma2(c[3][1], a23.y, b01.y);
        }
        __syncthreads();
    }

    float4 bias = *(const float4*)(bp + n0 + tx*4);
    #pragma unroll
    for (int i = 0; i < 4; ++i) {
        int r = m0 + ty*4 + i;
        float2 lo = unpk(c[i][0]);
        float2 hi = unpk(c[i][1]);
        *(float4*)(out + (size_t)r * CC + n0 + tx*4) =
            make_float4(lo.x + bias.x, lo.y + bias.y, hi.x + bias.z, hi.y + bias.w);
    }
}

// ---------------------------------------------------------------------------
extern "C" void kernel_launch(void* const* d_in, const int* in_sizes, int n_in,
                              void* d_out, int out_size)
{
    const float* x  = (const float*)d_in[0];
    const float* Wq = (const float*)d_in[1];
    const float* Wk = (const float*)d_in[2];
    const float* Wv = (const float*)d_in[3];
    const float* Wp = (const float*)d_in[4];
    const float* bp = (const float*)d_in[5];
    float* out = (float*)d_out;

    const int ATTN_SMEM = 2 * TT * DD * (int)sizeof(float);   // 128 KB
    cudaFuncSetAttribute(attn_kernel, cudaFuncAttributeMaxDynamicSharedMemorySize, ATTN_SMEM);

    qkv_kernel<<<dim3(BT/64, 3*HH), 256>>>(x, Wq, Wk, Wv);
    attn_kernel<<<dim3(BB*HH), 256, ATTN_SMEM>>>();
    proj_kernel<<<dim3(BT/64, CC/DD), 256>>>(Wp, bp, out);
}

// round 8
// speedup vs baseline: 1.9386x; 1.9386x over previous
#include <cuda_runtime.h>
#include <cuda_bf16.h>
#include <cstdint>

#define BB 64
#define TT 256
#define CC 384
#define HH 6
#define DD 64
#define BT (BB*TT)

// Scratch (device globals: allocation-free per harness rules)
__device__ float g_Q[BB*HH*TT*DD];   // [b][h][t][d]
__device__ float g_K[BB*HH*TT*DD];
__device__ float g_V[BB*HH*TT*DD];
__device__ float g_A[BB*TT*CC];      // attention out, [b][t][h*64+d]

// bf16 hi/lo split operands
__device__ __nv_bfloat16 g_Xh[BT*CC],  g_Xl[BT*CC];       // x rows [r][c]
__device__ __nv_bfloat16 g_Wth[3*CC*CC], g_Wtl[3*CC*CC];  // W^T [p][n=h*64+d][k]
__device__ __nv_bfloat16 g_Ah[BT*CC],  g_Al[BT*CC];       // attn out rows
__device__ __nv_bfloat16 g_Wph[CC*CC], g_Wpl[CC*CC];      // Wp^T [n][k]

// ---------------------------------------------------------------------------
__device__ __forceinline__ void mma16816(float* c, const uint32_t* a, uint32_t b0, uint32_t b1) {
    asm volatile("mma.sync.aligned.m16n8k16.row.col.f32.bf16.bf16.f32 "
                 "{%0,%1,%2,%3}, {%4,%5,%6,%7}, {%8,%9}, {%0,%1,%2,%3};"
                 : "+f"(c[0]), "+f"(c[1]), "+f"(c[2]), "+f"(c[3])
                 : "r"(a[0]), "r"(a[1]), "r"(a[2]), "r"(a[3]), "r"(b0), "r"(b1));
}
__device__ __forceinline__ uint32_t lds32(const __nv_bfloat16* p) {
    return *(const uint32_t*)p;
}

// ---------------------------------------------------------------------------
// Prep kernels: fp32 -> bf16 hi/lo splits (+ transposes for B operands)
// (these reference the device globals in DEVICE code: valid addresses)
// ---------------------------------------------------------------------------
__global__ __launch_bounds__(256) void conv_x(const float* __restrict__ x) {
    int i = blockIdx.x * 256 + threadIdx.x;
    float v = x[i];
    __nv_bfloat16 h = __float2bfloat16(v);
    g_Xh[i] = h;
    g_Xl[i] = __float2bfloat16(v - __bfloat162float(h));
}
__global__ __launch_bounds__(256) void conv_w(
    const float* __restrict__ Wq, const float* __restrict__ Wk, const float* __restrict__ Wv)
{
    int i = blockIdx.x * 256 + threadIdx.x;          // 3*384*384
    int p = i / (CC * CC);
    int rem = i - p * CC * CC;
    int n = rem / CC, k = rem - n * CC;
    int h = n >> 6, d = n & 63;
    const float* W = (p == 0 ? Wq : (p == 1 ? Wk : Wv));
    float v = W[(h * CC + k) * DD + d];
    __nv_bfloat16 hi = __float2bfloat16(v);
    g_Wth[i] = hi;
    g_Wtl[i] = __float2bfloat16(v - __bfloat162float(hi));
}
__global__ __launch_bounds__(256) void conv_wp(const float* __restrict__ Wp) {
    int i = blockIdx.x * 256 + threadIdx.x;          // 384*384
    int n = i / CC, k = i - n * CC;
    float v = Wp[k * CC + n];
    __nv_bfloat16 hi = __float2bfloat16(v);
    g_Wph[i] = hi;
    g_Wpl[i] = __float2bfloat16(v - __bfloat162float(hi));
}
__global__ __launch_bounds__(256) void conv_a() {
    int i = blockIdx.x * 256 + threadIdx.x;
    float v = g_A[i];
    __nv_bfloat16 h = __float2bfloat16(v);
    g_Ah[i] = h;
    g_Al[i] = __float2bfloat16(v - __bfloat162float(h));
}

// ---------------------------------------------------------------------------
// HMMA GEMM: C[M, 64-n-tile] = A[M,384] * B^T[n,384], bf16 hi/lo 3-pass.
// CTA 128m x 64n, 8 warps (32x32 warp tiles), K-chunks of 64.
// Fragments loaded by COORDINATE (PTX ISA tables) via LDS.32 from padded
// (stride-72) unswizzled smem. ALL device-global operands resolved in
// device code (host-passed __device__ symbols were the r5/r6 bug).
// mode 0: qkv (blockIdx.y = p*6+h2 -> g_Q/K/V [b][h][t][d])
// mode 1: proj (blockIdx.y = n-tile, out + bias)
// ---------------------------------------------------------------------------
#define ASTR 72
#define HS_AH 0
#define HS_AL (128*ASTR)
#define HS_BH (2*128*ASTR)
#define HS_BL (2*128*ASTR + 64*ASTR)
#define HS_TOT (2*128*ASTR + 2*64*ASTR)   // 27648 elems = 55296 B

__global__ __launch_bounds__(256) void hmma_gemm(
    int mode, const float* __restrict__ bias, float* __restrict__ outp)
{
    extern __shared__ __nv_bfloat16 hsm[];
    __nv_bfloat16* AsH = hsm + HS_AH;
    __nv_bfloat16* AsL = hsm + HS_AL;
    __nv_bfloat16* BsH = hsm + HS_BH;
    __nv_bfloat16* BsL = hsm + HS_BL;

    const int tid  = threadIdx.x;
    const int lane = tid & 31;
    const int wid  = tid >> 5;
    const int m0   = blockIdx.x * 128;

    int p = 0, h2;
    const __nv_bfloat16 *Ah, *Al, *Bh, *Bl;
    float* O;
    if (mode == 0) {
        p = blockIdx.y / 6; h2 = blockIdx.y % 6;
        Ah = g_Xh; Al = g_Xl;
        Bh = g_Wth + p * CC * CC + h2 * 64 * CC;
        Bl = g_Wtl + p * CC * CC + h2 * 64 * CC;
        O  = (p == 0 ? g_Q : (p == 1 ? g_K : g_V));
    } else {
        h2 = blockIdx.y;
        Ah = g_Ah; Al = g_Al;
        Bh = g_Wph + h2 * 64 * CC;
        Bl = g_Wpl + h2 * 64 * CC;
        O  = outp;
    }

    const int wm = (wid & 3) * 32;     // warp m-offset
    const int wn = (wid >> 2) * 32;    // warp n-offset
    const int grp = lane >> 2;         // fragment row group 0..7
    const int tig = lane & 3;          // thread-in-group

    float c[2][4][4] = {};

    for (int ch = 0; ch < 6; ++ch) {
        const int kb = ch * 64;
        // A: 128 rows x 64 bf16, 8 chunks of 16B per row, stride 72 elems
        #pragma unroll
        for (int j = 0; j < 4; ++j) {
            int i = tid + j * 256;
            int row = i >> 3, q8 = i & 7;
            int dst = row * ASTR + q8 * 8;
            int gi  = (m0 + row) * CC + kb + q8 * 8;
            *(uint4*)(AsH + dst) = *(const uint4*)(Ah + gi);
            *(uint4*)(AsL + dst) = *(const uint4*)(Al + gi);
        }
        // B: 64 rows x 64 bf16
        #pragma unroll
        for (int j = 0; j < 2; ++j) {
            int i = tid + j * 256;
            int row = i >> 3, q8 = i & 7;
            int dst = row * ASTR + q8 * 8;
            int gi  = row * CC + kb + q8 * 8;
            *(uint4*)(BsH + dst) = *(const uint4*)(Bh + gi);
            *(uint4*)(BsL + dst) = *(const uint4*)(Bl + gi);
        }
        __syncthreads();

        #pragma unroll
        for (int ks = 0; ks < 4; ++ks) {
            const int kofs = ks * 16 + 2 * tig;
            uint32_t ah[2][4], al[2][4], bh[2][4], bl[2][4];
            // A fragments: a0=(grp,k) a1=(grp+8,k) a2=(grp,k+8) a3=(grp+8,k+8)
            #pragma unroll
            for (int mi = 0; mi < 2; ++mi) {
                const __nv_bfloat16* pH = AsH + (wm + mi * 16 + grp) * ASTR + kofs;
                const __nv_bfloat16* pL = AsL + (wm + mi * 16 + grp) * ASTR + kofs;
                ah[mi][0] = lds32(pH);
                ah[mi][1] = lds32(pH + 8 * ASTR);
                ah[mi][2] = lds32(pH + 8);
                ah[mi][3] = lds32(pH + 8 * ASTR + 8);
                al[mi][0] = lds32(pL);
                al[mi][1] = lds32(pL + 8 * ASTR);
                al[mi][2] = lds32(pL + 8);
                al[mi][3] = lds32(pL + 8 * ASTR + 8);
            }
            // B fragments from B^T[n][k]: b0=(k=2tig, n=grp), b1=(k+8, n=grp)
            #pragma unroll
            for (int nb = 0; nb < 2; ++nb) {
                const __nv_bfloat16* pH = BsH + (wn + nb * 16 + grp) * ASTR + kofs;
                const __nv_bfloat16* pL = BsL + (wn + nb * 16 + grp) * ASTR + kofs;
                bh[nb][0] = lds32(pH);
                bh[nb][1] = lds32(pH + 8);
                bh[nb][2] = lds32(pH + 8 * ASTR);
                bh[nb][3] = lds32(pH + 8 * ASTR + 8);
                bl[nb][0] = lds32(pL);
                bl[nb][1] = lds32(pL + 8);
                bl[nb][2] = lds32(pL + 8 * ASTR);
                bl[nb][3] = lds32(pL + 8 * ASTR + 8);
            }
            #pragma unroll
            for (int mi = 0; mi < 2; ++mi) {
                #pragma unroll
                for (int ni = 0; ni < 4; ++ni) {
                    uint32_t b0h = bh[ni >> 1][(ni & 1) * 2], b1h = bh[ni >> 1][(ni & 1) * 2 + 1];
                    uint32_t b0l = bl[ni >> 1][(ni & 1) * 2], b1l = bl[ni >> 1][(ni & 1) * 2 + 1];
                    mma16816(c[mi][ni], ah[mi], b0h, b1h);   // hh
                    mma16816(c[mi][ni], ah[mi], b0l, b1l);   // hl
                    mma16816(c[mi][ni], al[mi], b0h, b1h);   // lh
                }
            }
        }
        __syncthreads();
    }

    // Epilogue: c0,c1=(grp, 2tig..+1); c2,c3=(grp+8, ..)
    #pragma unroll
    for (int mi = 0; mi < 2; ++mi) {
        #pragma unroll
        for (int ni = 0; ni < 4; ++ni) {
            int row0 = m0 + wm + mi * 16 + grp;
            int col  = wn + ni * 8 + tig * 2;
            if (mode == 0) {
                int b0i = row0 >> 8, t0 = row0 & 255;
                int r1 = row0 + 8, b1i = r1 >> 8, t1 = r1 & 255;
                *(float2*)(O + ((b0i * HH + h2) * TT + t0) * DD + col) =
                    make_float2(c[mi][ni][0], c[mi][ni][1]);
                *(float2*)(O + ((b1i * HH + h2) * TT + t1) * DD + col) =
                    make_float2(c[mi][ni][2], c[mi][ni][3]);
            } else {
                int n = h2 * 64 + col;
                float2 bv = *(const float2*)(bias + n);
                *(float2*)(O + (size_t)row0 * CC + n) =
                    make_float2(c[mi][ni][0] + bv.x, c[mi][ni][1] + bv.y);
                *(float2*)(O + (size_t)(row0 + 8) * CC + n) =
                    make_float2(c[mi][ni][2] + bv.x, c[mi][ni][3] + bv.y);
            }
        }
    }
}

// ---------------------------------------------------------------------------
// Fused causal attention (scalar fp32, round-2 version; globals in device code)
// ---------------------------------------------------------------------------
__global__ __launch_bounds__(256) void attn_kernel()
{
    extern __shared__ float sm[];
    float* Ks = sm;
    float* Vs = sm + TT*DD;

    const int bh  = blockIdx.x;
    const int tid = threadIdx.x;

    const float4* kg4 = (const float4*)(g_K + (size_t)bh * TT * DD);
    const float4* vg4 = (const float4*)(g_V + (size_t)bh * TT * DD);
    float4* Ks4 = (float4*)Ks;
    float4* Vs4 = (float4*)Vs;
    #pragma unroll
    for (int i = 0; i < (TT*DD/4)/256; ++i) {
        Ks4[tid + i*256] = kg4[tid + i*256];
        Vs4[tid + i*256] = vg4[tid + i*256];
    }
    __syncthreads();

    const int t = tid;
    float q[64];
    {
        const float4* qg = (const float4*)(g_Q + ((size_t)bh * TT + t) * DD);
        #pragma unroll
        for (int i = 0; i < 16; ++i) {
            float4 v = qg[i];
            q[4*i+0] = v.x; q[4*i+1] = v.y; q[4*i+2] = v.z; q[4*i+3] = v.w;
        }
    }

    float acc[64];
    #pragma unroll
    for (int i = 0; i < 64; ++i) acc[i] = 0.0f;
    float l = 0.0f;
    const float scale = 0.125f;

    for (int s = 0; s <= t; ++s) {
        const float4* krow = (const float4*)(Ks + s * DD);
        float sc = 0.0f;
        #pragma unroll
        for (int i = 0; i < 16; ++i) {
            float4 kv = krow[i];
            sc += q[4*i+0]*kv.x + q[4*i+1]*kv.y + q[4*i+2]*kv.z + q[4*i+3]*kv.w;
        }
        float e = __expf(sc * scale);
        l += e;
        const float4* vrow = (const float4*)(Vs + s * DD);
        #pragma unroll
        for (int i = 0; i < 16; ++i) {
            float4 vv = vrow[i];
            acc[4*i+0] += e * vv.x;
            acc[4*i+1] += e * vv.y;
            acc[4*i+2] += e * vv.z;
            acc[4*i+3] += e * vv.w;
        }
    }

    const float inv = 1.0f / l;
    const int b = bh / HH, h = bh % HH;
    float4* og = (float4*)(g_A + ((size_t)(b*TT + t)) * CC + h * DD);
    #pragma unroll
    for (int i = 0; i < 16; ++i) {
        og[i] = make_float4(acc[4*i+0]*inv, acc[4*i+1]*inv,
                            acc[4*i+2]*inv, acc[4*i+3]*inv);
    }
}

// ---------------------------------------------------------------------------
extern "C" void kernel_launch(void* const* d_in, const int* in_sizes, int n_in,
                              void* d_out, int out_size)
{
    const float* x  = (const float*)d_in[0];
    const float* Wq = (const float*)d_in[1];
    const float* Wk = (const float*)d_in[2];
    const float* Wv = (const float*)d_in[3];
    const float* Wp = (const float*)d_in[4];
    const float* bp = (const float*)d_in[5];
    float* out = (float*)d_out;

    const int ATTN_SMEM = 2 * TT * DD * (int)sizeof(float);       // 128 KB
    const int HMMA_SMEM = HS_TOT * (int)sizeof(__nv_bfloat16);    // 55296 B
    cudaFuncSetAttribute(attn_kernel, cudaFuncAttributeMaxDynamicSharedMemorySize, ATTN_SMEM);
    cudaFuncSetAttribute(hmma_gemm, cudaFuncAttributeMaxDynamicSharedMemorySize, HMMA_SMEM);

    conv_x<<<BT*CC/256, 256>>>(x);
    conv_w<<<3*CC*CC/256, 256>>>(Wq, Wk, Wv);
    conv_wp<<<CC*CC/256, 256>>>(Wp);
    hmma_gemm<<<dim3(BT/128, 18), 256, HMMA_SMEM>>>(0, nullptr, nullptr);
    attn_kernel<<<dim3(BB*HH), 256, ATTN_SMEM>>>();
    conv_a<<<BT*CC/256, 256>>>();
    hmma_gemm<<<dim3(BT/128, 6), 256, HMMA_SMEM>>>(1, bp, out);
}

// round 9
// speedup vs baseline: 2.8946x; 1.4932x over previous
#include <cuda_runtime.h>
#include <cuda_bf16.h>
#include <cstdint>

#define BB 64
#define TT 256
#define CC 384
#define HH 6
#define DD 64
#define BT (BB*TT)

// Scratch (device globals: allocation-free per harness rules)
__device__ float g_Q[BB*HH*TT*DD];   // [b][h][t][d]
__device__ float g_K[BB*HH*TT*DD];
__device__ float g_V[BB*HH*TT*DD];

// bf16 hi/lo split operands
__device__ __nv_bfloat16 g_Xh[BT*CC],  g_Xl[BT*CC];       // x rows [r][c]
__device__ __nv_bfloat16 g_Wth[3*CC*CC], g_Wtl[3*CC*CC];  // W^T [p][n=h*64+d][k]
__device__ __nv_bfloat16 g_Ah[BT*CC],  g_Al[BT*CC];       // attn out rows [r][c]
__device__ __nv_bfloat16 g_Wph[CC*CC], g_Wpl[CC*CC];      // Wp^T [n][k]

// ---------------------------------------------------------------------------
__device__ __forceinline__ void mma16816(float* c, const uint32_t* a, uint32_t b0, uint32_t b1) {
    asm volatile("mma.sync.aligned.m16n8k16.row.col.f32.bf16.bf16.f32 "
                 "{%0,%1,%2,%3}, {%4,%5,%6,%7}, {%8,%9}, {%0,%1,%2,%3};"
                 : "+f"(c[0]), "+f"(c[1]), "+f"(c[2]), "+f"(c[3])
                 : "r"(a[0]), "r"(a[1]), "r"(a[2]), "r"(a[3]), "r"(b0), "r"(b1));
}
__device__ __forceinline__ uint32_t lds32(const __nv_bfloat16* p) {
    return *(const uint32_t*)p;
}
// split (a,b) fp32 pair into packed bf16x2 hi and lo
__device__ __forceinline__ void split_pair(float a, float b, uint32_t& h, uint32_t& l) {
    __nv_bfloat16 ah = __float2bfloat16(a), bh = __float2bfloat16(b);
    __nv_bfloat162 hv; hv.x = ah; hv.y = bh;
    h = *(uint32_t*)&hv;
    __nv_bfloat162 lv = __floats2bfloat162_rn(a - __bfloat162float(ah),
                                              b - __bfloat162float(bh));
    l = *(uint32_t*)&lv;
}

// ---------------------------------------------------------------------------
// Prep kernels: fp32 -> bf16 hi/lo splits (+ transposes for B operands)
// ---------------------------------------------------------------------------
__global__ __launch_bounds__(256) void conv_x(const float* __restrict__ x) {
    int i = blockIdx.x * 256 + threadIdx.x;
    float v = x[i];
    __nv_bfloat16 h = __float2bfloat16(v);
    g_Xh[i] = h;
    g_Xl[i] = __float2bfloat16(v - __bfloat162float(h));
}
__global__ __launch_bounds__(256) void conv_w(
    const float* __restrict__ Wq, const float* __restrict__ Wk, const float* __restrict__ Wv)
{
    int i = blockIdx.x * 256 + threadIdx.x;          // 3*384*384
    int p = i / (CC * CC);
    int rem = i - p * CC * CC;
    int n = rem / CC, k = rem - n * CC;
    int h = n >> 6, d = n & 63;
    const float* W = (p == 0 ? Wq : (p == 1 ? Wk : Wv));
    float v = W[(h * CC + k) * DD + d];
    __nv_bfloat16 hi = __float2bfloat16(v);
    g_Wth[i] = hi;
    g_Wtl[i] = __float2bfloat16(v - __bfloat162float(hi));
}
__global__ __launch_bounds__(256) void conv_wp(const float* __restrict__ Wp) {
    int i = blockIdx.x * 256 + threadIdx.x;          // 384*384
    int n = i / CC, k = i - n * CC;
    float v = Wp[k * CC + n];
    __nv_bfloat16 hi = __float2bfloat16(v);
    g_Wph[i] = hi;
    g_Wpl[i] = __float2bfloat16(v - __bfloat162float(hi));
}

// ---------------------------------------------------------------------------
// HMMA GEMM (validated round 8): C[M,64-tile] = A[M,384]*B^T[n,384], 3-pass.
// ---------------------------------------------------------------------------
#define ASTR 72
#define HS_AH 0
#define HS_AL (128*ASTR)
#define HS_BH (2*128*ASTR)
#define HS_BL (2*128*ASTR + 64*ASTR)
#define HS_TOT (2*128*ASTR + 2*64*ASTR)   // 27648 elems = 55296 B

__global__ __launch_bounds__(256) void hmma_gemm(
    int mode, const float* __restrict__ bias, float* __restrict__ outp)
{
    extern __shared__ __nv_bfloat16 hsm[];
    __nv_bfloat16* AsH = hsm + HS_AH;
    __nv_bfloat16* AsL = hsm + HS_AL;
    __nv_bfloat16* BsH = hsm + HS_BH;
    __nv_bfloat16* BsL = hsm + HS_BL;

    const int tid  = threadIdx.x;
    const int lane = tid & 31;
    const int wid  = tid >> 5;
    const int m0   = blockIdx.x * 128;

    int p = 0, h2;
    const __nv_bfloat16 *Ah, *Al, *Bh, *Bl;
    float* O;
    if (mode == 0) {
        p = blockIdx.y / 6; h2 = blockIdx.y % 6;
        Ah = g_Xh; Al = g_Xl;
        Bh = g_Wth + p * CC * CC + h2 * 64 * CC;
        Bl = g_Wtl + p * CC * CC + h2 * 64 * CC;
        O  = (p == 0 ? g_Q : (p == 1 ? g_K : g_V));
    } else {
        h2 = blockIdx.y;
        Ah = g_Ah; Al = g_Al;
        Bh = g_Wph + h2 * 64 * CC;
        Bl = g_Wpl + h2 * 64 * CC;
        O  = outp;
    }

    const int wm = (wid & 3) * 32;
    const int wn = (wid >> 2) * 32;
    const int grp = lane >> 2;
    const int tig = lane & 3;

    float c[2][4][4] = {};

    for (int ch = 0; ch < 6; ++ch) {
        const int kb = ch * 64;
        #pragma unroll
        for (int j = 0; j < 4; ++j) {
            int i = tid + j * 256;
            int row = i >> 3, q8 = i & 7;
            int dst = row * ASTR + q8 * 8;
            int gi  = (m0 + row) * CC + kb + q8 * 8;
            *(uint4*)(AsH + dst) = *(const uint4*)(Ah + gi);
            *(uint4*)(AsL + dst) = *(const uint4*)(Al + gi);
        }
        #pragma unroll
        for (int j = 0; j < 2; ++j) {
            int i = tid + j * 256;
            int row = i >> 3, q8 = i & 7;
            int dst = row * ASTR + q8 * 8;
            int gi  = row * CC + kb + q8 * 8;
            *(uint4*)(BsH + dst) = *(const uint4*)(Bh + gi);
            *(uint4*)(BsL + dst) = *(const uint4*)(Bl + gi);
        }
        __syncthreads();

        #pragma unroll
        for (int ks = 0; ks < 4; ++ks) {
            const int kofs = ks * 16 + 2 * tig;
            uint32_t ah[2][4], al[2][4], bh[2][4], bl[2][4];
            #pragma unroll
            for (int mi = 0; mi < 2; ++mi) {
                const __nv_bfloat16* pH = AsH + (wm + mi * 16 + grp) * ASTR + kofs;
                const __nv_bfloat16* pL = AsL + (wm + mi * 16 + grp) * ASTR + kofs;
                ah[mi][0] = lds32(pH);
                ah[mi][1] = lds32(pH + 8 * ASTR);
                ah[mi][2] = lds32(pH + 8);
                ah[mi][3] = lds32(pH + 8 * ASTR + 8);
                al[mi][0] = lds32(pL);
                al[mi][1] = lds32(pL + 8 * ASTR);
                al[mi][2] = lds32(pL + 8);
                al[mi][3] = lds32(pL + 8 * ASTR + 8);
            }
            #pragma unroll
            for (int nb = 0; nb < 2; ++nb) {
                const __nv_bfloat16* pH = BsH + (wn + nb * 16 + grp) * ASTR + kofs;
                const __nv_bfloat16* pL = BsL + (wn + nb * 16 + grp) * ASTR + kofs;
                bh[nb][0] = lds32(pH);
                bh[nb][1] = lds32(pH + 8);
                bh[nb][2] = lds32(pH + 8 * ASTR);
                bh[nb][3] = lds32(pH + 8 * ASTR + 8);
                bl[nb][0] = lds32(pL);
                bl[nb][1] = lds32(pL + 8);
                bl[nb][2] = lds32(pL + 8 * ASTR);
                bl[nb][3] = lds32(pL + 8 * ASTR + 8);
            }
            #pragma unroll
            for (int mi = 0; mi < 2; ++mi) {
                #pragma unroll
                for (int ni = 0; ni < 4; ++ni) {
                    uint32_t b0h = bh[ni >> 1][(ni & 1) * 2], b1h = bh[ni >> 1][(ni & 1) * 2 + 1];
                    uint32_t b0l = bl[ni >> 1][(ni & 1) * 2], b1l = bl[ni >> 1][(ni & 1) * 2 + 1];
                    mma16816(c[mi][ni], ah[mi], b0h, b1h);
                    mma16816(c[mi][ni], ah[mi], b0l, b1l);
                    mma16816(c[mi][ni], al[mi], b0h, b1h);
                }
            }
        }
        __syncthreads();
    }

    #pragma unroll
    for (int mi = 0; mi < 2; ++mi) {
        #pragma unroll
        for (int ni = 0; ni < 4; ++ni) {
            int row0 = m0 + wm + mi * 16 + grp;
            int col  = wn + ni * 8 + tig * 2;
            if (mode == 0) {
                int b0i = row0 >> 8, t0 = row0 & 255;
                int r1 = row0 + 8, b1i = r1 >> 8, t1 = r1 & 255;
                *(float2*)(O + ((b0i * HH + h2) * TT + t0) * DD + col) =
                    make_float2(c[mi][ni][0], c[mi][ni][1]);
                *(float2*)(O + ((b1i * HH + h2) * TT + t1) * DD + col) =
                    make_float2(c[mi][ni][2], c[mi][ni][3]);
            } else {
                int n = h2 * 64 + col;
                float2 bv = *(const float2*)(bias + n);
                *(float2*)(O + (size_t)row0 * CC + n) =
                    make_float2(c[mi][ni][0] + bv.x, c[mi][ni][1] + bv.y);
                *(float2*)(O + (size_t)(row0 + 8) * CC + n) =
                    make_float2(c[mi][ni][2] + bv.x, c[mi][ni][3] + bv.y);
            }
        }
    }
}

// ---------------------------------------------------------------------------
// Flash-style HMMA causal attention. One CTA per (b,h), 8 warps.
// Q/K hi/lo bf16 stride-72; V transposed Vt[d][s] stride-264 (both ≡4 words
// mod 32 -> conflict-free coordinate frag loads). Warp w owns q-tiles w and
// 15-w (exactly 5 causal key-blocks each). P fragments come straight from
// S C-fragments (no smem). No-max softmax; 3-pass hi/lo on QK and PV.
// Writes g_Ah/g_Al directly (bf16 hi/lo), eliminating conv_a.
// ---------------------------------------------------------------------------
#define QSTR 72
#define VSTR 264
#define AF_QH 0
#define AF_QL (256*QSTR)
#define AF_KH (2*256*QSTR)
#define AF_KL (3*256*QSTR)
#define AF_VH (4*256*QSTR)
#define AF_VL (4*256*QSTR + 64*VSTR)
#define AF_TOT (4*256*QSTR + 2*64*VSTR)   // 107520 elems = 215040 B

__global__ __launch_bounds__(256) void attn_flash()
{
    extern __shared__ __nv_bfloat16 asm_[];
    __nv_bfloat16* Qh = asm_ + AF_QH;
    __nv_bfloat16* Ql = asm_ + AF_QL;
    __nv_bfloat16* Kh = asm_ + AF_KH;
    __nv_bfloat16* Kl = asm_ + AF_KL;
    __nv_bfloat16* Vh = asm_ + AF_VH;
    __nv_bfloat16* Vl = asm_ + AF_VL;

    const int bh  = blockIdx.x;
    const int tid = threadIdx.x;
    const int lane = tid & 31;
    const int wid  = tid >> 5;
    const int grp  = lane >> 2;
    const int tig  = lane & 3;

    // ---- load Q,K (row-major, stride 72) and V transposed (Vt[d][s], 264) --
    const float4* Qg = (const float4*)(g_Q + (size_t)bh * TT * DD);
    const float4* Kg = (const float4*)(g_K + (size_t)bh * TT * DD);
    const float4* Vg = (const float4*)(g_V + (size_t)bh * TT * DD);
    #pragma unroll
    for (int j = 0; j < 16; ++j) {
        int i4 = tid + j * 256;              // 4096 float4s
        int row = i4 >> 4, c4 = (i4 & 15) * 4;
        float4 qv = Qg[i4];
        uint32_t h0, l0, h1, l1;
        split_pair(qv.x, qv.y, h0, l0);
        split_pair(qv.z, qv.w, h1, l1);
        *(uint32_t*)(Qh + row * QSTR + c4)     = h0;
        *(uint32_t*)(Qh + row * QSTR + c4 + 2) = h1;
        *(uint32_t*)(Ql + row * QSTR + c4)     = l0;
        *(uint32_t*)(Ql + row * QSTR + c4 + 2) = l1;
        float4 kv = Kg[i4];
        split_pair(kv.x, kv.y, h0, l0);
        split_pair(kv.z, kv.w, h1, l1);
        *(uint32_t*)(Kh + row * QSTR + c4)     = h0;
        *(uint32_t*)(Kh + row * QSTR + c4 + 2) = h1;
        *(uint32_t*)(Kl + row * QSTR + c4)     = l0;
        *(uint32_t*)(Kl + row * QSTR + c4 + 2) = l1;
    }
    #pragma unroll
    for (int j = 0; j < 16; ++j) {
        int i4 = tid + j * 256;              // d-major mapping for transpose
        int d4 = i4 >> 8, s = i4 & 255;
        float4 vv = Vg[s * 16 + d4];
        float e[4] = {vv.x, vv.y, vv.z, vv.w};
        #pragma unroll
        for (int q = 0; q < 4; ++q) {
            int d = d4 * 4 + q;
            __nv_bfloat16 hb = __float2bfloat16(e[q]);
            Vh[d * VSTR + s] = hb;
            Vl[d * VSTR + s] = __float2bfloat16(e[q] - __bfloat162float(hb));
        }
    }
    __syncthreads();

    const float scale = 0.125f;
    const int b  = bh / HH, h = bh % HH;
    const int rbase = b * TT;

    #pragma unroll
    for (int mi = 0; mi < 2; ++mi) {
        const int tile = (mi == 0) ? wid : 15 - wid;
        const int m_lo = tile * 16;
        const int nkb  = (m_lo >> 6) + 1;
        const int r0 = m_lo + grp, r1 = r0 + 8;

        float o[8][4];
        #pragma unroll
        for (int ni = 0; ni < 8; ++ni)
            #pragma unroll
            for (int q = 0; q < 4; ++q) o[ni][q] = 0.0f;
        float lsum0 = 0.0f, lsum1 = 0.0f;

        for (int kb = 0; kb < nkb; ++kb) {
            float s[8][4];
            #pragma unroll
            for (int ni = 0; ni < 8; ++ni)
                #pragma unroll
                for (int q = 0; q < 4; ++q) s[ni][q] = 0.0f;

            // ---- S = Q Kb^T -------------------------------------------------
            #pragma unroll
            for (int ks = 0; ks < 4; ++ks) {
                const int kofs = ks * 16 + 2 * tig;
                const __nv_bfloat16* qH = Qh + (m_lo + grp) * QSTR + kofs;
                const __nv_bfloat16* qL = Ql + (m_lo + grp) * QSTR + kofs;
                uint32_t aH[4] = { lds32(qH), lds32(qH + 8 * QSTR),
                                   lds32(qH + 8), lds32(qH + 8 * QSTR + 8) };
                uint32_t aL[4] = { lds32(qL), lds32(qL + 8 * QSTR),
                                   lds32(qL + 8), lds32(qL + 8 * QSTR + 8) };
                uint32_t bH[4][4], bL[4][4];
                #pragma unroll
                for (int nb = 0; nb < 4; ++nb) {
                    const __nv_bfloat16* kH = Kh + (kb * 64 + nb * 16 + grp) * QSTR + kofs;
                    const __nv_bfloat16* kL = Kl + (kb * 64 + nb * 16 + grp) * QSTR + kofs;
                    bH[nb][0] = lds32(kH);           bH[nb][1] = lds32(kH + 8);
                    bH[nb][2] = lds32(kH + 8*QSTR);  bH[nb][3] = lds32(kH + 8*QSTR + 8);
                    bL[nb][0] = lds32(kL);           bL[nb][1] = lds32(kL + 8);
                    bL[nb][2] = lds32(kL + 8*QSTR);  bL[nb][3] = lds32(kL + 8*QSTR + 8);
                }
                #pragma unroll
                for (int ni = 0; ni < 8; ++ni) {
                    uint32_t b0h = bH[ni >> 1][(ni & 1) * 2], b1h = bH[ni >> 1][(ni & 1) * 2 + 1];
                    uint32_t b0l = bL[ni >> 1][(ni & 1) * 2], b1l = bL[ni >> 1][(ni & 1) * 2 + 1];
                    mma16816(s[ni], aH, b0h, b1h);
                    mma16816(s[ni], aH, b0l, b1l);
                    mma16816(s[ni], aL, b0h, b1h);
                }
            }

            // ---- softmax weights (no-max; causal mask) ----------------------
            #pragma unroll
            for (int ni = 0; ni < 8; ++ni) {
                const int c0 = kb * 64 + ni * 8 + 2 * tig, c1 = c0 + 1;
                float e0 = (c0 <= r0) ? __expf(s[ni][0] * scale) : 0.0f;
                float e1 = (c1 <= r0) ? __expf(s[ni][1] * scale) : 0.0f;
                float e2 = (c0 <= r1) ? __expf(s[ni][2] * scale) : 0.0f;
                float e3 = (c1 <= r1) ? __expf(s[ni][3] * scale) : 0.0f;
                lsum0 += e0 + e1;
                lsum1 += e2 + e3;
                s[ni][0] = e0; s[ni][1] = e1; s[ni][2] = e2; s[ni][3] = e3;
            }

            // ---- O += P Vb  (P frags direct from S C-frags) -----------------
            #pragma unroll
            for (int ksv = 0; ksv < 4; ++ksv) {
                uint32_t paH[4], paL[4];
                split_pair(s[2*ksv][0],   s[2*ksv][1],   paH[0], paL[0]);
                split_pair(s[2*ksv][2],   s[2*ksv][3],   paH[1], paL[1]);
                split_pair(s[2*ksv+1][0], s[2*ksv+1][1], paH[2], paL[2]);
                split_pair(s[2*ksv+1][2], s[2*ksv+1][3], paH[3], paL[3]);
                const int colv = kb * 64 + ksv * 16 + 2 * tig;
                uint32_t vbH[4][4], vbL[4][4];
                #pragma unroll
                for (int nb = 0; nb < 4; ++nb) {
                    const __nv_bfloat16* vH = Vh + (nb * 16 + grp) * VSTR + colv;
                    const __nv_bfloat16* vL = Vl + (nb * 16 + grp) * VSTR + colv;
                    vbH[nb][0] = lds32(vH);           vbH[nb][1] = lds32(vH + 8);
                    vbH[nb][2] = lds32(vH + 8*VSTR);  vbH[nb][3] = lds32(vH + 8*VSTR + 8);
                    vbL[nb][0] = lds32(vL);           vbL[nb][1] = lds32(vL + 8);
                    vbL[nb][2] = lds32(vL + 8*VSTR);  vbL[nb][3] = lds32(vL + 8*VSTR + 8);
                }
                #pragma unroll
                for (int ni = 0; ni < 8; ++ni) {
                    uint32_t b0h = vbH[ni >> 1][(ni & 1) * 2], b1h = vbH[ni >> 1][(ni & 1) * 2 + 1];
                    uint32_t b0l = vbL[ni >> 1][(ni & 1) * 2], b1l = vbL[ni >> 1][(ni & 1) * 2 + 1];
                    mma16816(o[ni], paH, b0h, b1h);
                    mma16816(o[ni], paL, b0h, b1h);
                    mma16816(o[ni], paH, b0l, b1l);
                }
            }
        }

        // ---- finalize: 1/l, hi/lo split, write g_Ah/g_Al --------------------
        lsum0 += __shfl_xor_sync(0xffffffffu, lsum0, 1);
        lsum0 += __shfl_xor_sync(0xffffffffu, lsum0, 2);
        lsum1 += __shfl_xor_sync(0xffffffffu, lsum1, 1);
        lsum1 += __shfl_xor_sync(0xffffffffu, lsum1, 2);
        const float inv0 = 1.0f / lsum0, inv1 = 1.0f / lsum1;

        #pragma unroll
        for (int ni = 0; ni < 8; ++ni) {
            const int col = h * 64 + ni * 8 + 2 * tig;
            uint32_t hv, lv;
            split_pair(o[ni][0] * inv0, o[ni][1] * inv0, hv, lv);
            *(uint32_t*)(g_Ah + (size_t)(rbase + r0) * CC + col) = hv;
            *(uint32_t*)(g_Al + (size_t)(rbase + r0) * CC + col) = lv;
            split_pair(o[ni][2] * inv1, o[ni][3] * inv1, hv, lv);
            *(uint32_t*)(g_Ah + (size_t)(rbase + r1) * CC + col) = hv;
            *(uint32_t*)(g_Al + (size_t)(rbase + r1) * CC + col) = lv;
        }
    }
}

// ---------------------------------------------------------------------------
extern "C" void kernel_launch(void* const* d_in, const int* in_sizes, int n_in,
                              void* d_out, int out_size)
{
    const float* x  = (const float*)d_in[0];
    const float* Wq = (const float*)d_in[1];
    const float* Wk = (const float*)d_in[2];
    const float* Wv = (const float*)d_in[3];
    const float* Wp = (const float*)d_in[4];
    const float* bp = (const float*)d_in[5];
    float* out = (float*)d_out;

    const int HMMA_SMEM = HS_TOT * (int)sizeof(__nv_bfloat16);    // 55296 B
    const int ATTN_SMEM = AF_TOT * (int)sizeof(__nv_bfloat16);    // 215040 B
    cudaFuncSetAttribute(hmma_gemm, cudaFuncAttributeMaxDynamicSharedMemorySize, HMMA_SMEM);
    cudaFuncSetAttribute(attn_flash, cudaFuncAttributeMaxDynamicSharedMemorySize, ATTN_SMEM);

    conv_x<<<BT*CC/256, 256>>>(x);
    conv_w<<<3*CC*CC/256, 256>>>(Wq, Wk, Wv);
    conv_wp<<<CC*CC/256, 256>>>(Wp);
    hmma_gemm<<<dim3(BT/128, 18), 256, HMMA_SMEM>>>(0, nullptr, nullptr);
    attn_flash<<<BB*HH, 256, ATTN_SMEM>>>();
    hmma_gemm<<<dim3(BT/128, 6), 256, HMMA_SMEM>>>(1, bp, out);
}